// round 4
// baseline (speedup 1.0000x reference)
#include <cuda_runtime.h>

// Geometry
#define HH   512
#define W4   128           // 512 floats / 4 per quad
#define TC   6             // t-chunks
#define TPC  33            // 198 / 6
#define GX   4             // 128 quads / 32 lanes
#define GY   64            // 512 rows / 8 rows-per-block
#define NBLK (GX*GY*TC)    // 1536

#define DENOM 52107462.0   // 198 * 513 * 513

typedef unsigned long long u64;

__device__ float g_part[NBLK * 2];
__device__ unsigned int g_count = 0;

// ---------- packed f32x2 helpers ----------
__device__ __forceinline__ u64 pk(float a, float b) {
    u64 r; asm("mov.b64 %0, {%1, %2};" : "=l"(r) : "f"(a), "f"(b)); return r;
}
__device__ __forceinline__ void upk(u64 v, float& a, float& b) {
    asm("mov.b64 {%0, %1}, %2;" : "=f"(a), "=f"(b) : "l"(v));
}
__device__ __forceinline__ u64 fadd2(u64 a, u64 b) {
    u64 d; asm("add.rn.f32x2 %0, %1, %2;" : "=l"(d) : "l"(a), "l"(b)); return d;
}
__device__ __forceinline__ u64 fsub2(u64 a, u64 b) {
    u64 d; asm("sub.rn.f32x2 %0, %1, %2;" : "=l"(d) : "l"(a), "l"(b)); return d;
}
__device__ __forceinline__ u64 fmul2(u64 a, u64 b) {
    u64 d; asm("mul.rn.f32x2 %0, %1, %2;" : "=l"(d) : "l"(a), "l"(b)); return d;
}
__device__ __forceinline__ u64 ffma2(u64 a, u64 b, u64 c) {
    u64 d; asm("fma.rn.f32x2 %0, %1, %2, %3;" : "=l"(d) : "l"(a), "l"(b), "l"(c)); return d;
}

// Laplacian (MU-folded) and time-difference for one channel-row.
__device__ __forceinline__ void lap_d(
    u64 clo, u64 chi, u64 lhi, u64 rlo,
    u64 n1lo, u64 n1hi, u64 p1lo, u64 p1hi,
    u64 n2lo, u64 n2hi, u64 p2lo, u64 p2hi,
    u64 nxlo, u64 nxhi,
    u64 CC, u64 CN, u64 CF,
    u64& laplo, u64& laphi, u64& dlo, u64& dhi)
{
    float c0, c1, c2, c3, lz, lw, r0, r1;
    upk(clo, c0, c1); upk(chi, c2, c3); upk(lhi, lz, lw); upk(rlo, r0, r1);
    const u64 m1 = pk(lw, c0);
    const u64 m2 = pk(c1, c2);
    const u64 m3 = pk(c3, r0);
    const u64 njlo = fadd2(m1, m2),  njhi = fadd2(m2, m3);
    const u64 fjlo = fadd2(lhi, chi), fjhi = fadd2(clo, rlo);
    const u64 nilo = fadd2(n1lo, p1lo), nihi = fadd2(n1hi, p1hi);
    const u64 filo = fadd2(n2lo, p2lo), fihi = fadd2(n2hi, p2hi);
    const u64 nearlo = fadd2(njlo, nilo), nearhi = fadd2(njhi, nihi);
    const u64 farlo  = fadd2(fjlo, filo), farhi  = fadd2(fjhi, fihi);
    laplo = ffma2(CN, nearlo, ffma2(CF, farlo, fmul2(CC, clo)));
    laphi = ffma2(CN, nearhi, ffma2(CF, farhi, fmul2(CC, chi)));
    dlo = fsub2(nxlo, clo);
    dhi = fsub2(nxhi, chi);
}

__global__ __launch_bounds__(256, 3)
void pde_kernel(const float* __restrict__ inF, float* __restrict__ out)
{
    // smem halo tile: 12 rows (block rows -2..9) x 32 quads x 2 channels
    __shared__ ulonglong2 smu[12 * 32];
    __shared__ ulonglong2 smv[12 * 32];

    const int tx = threadIdx.x;             // lane
    const int ty = threadIdx.y;             // warp = one row
    const int jb = blockIdx.x * 32 + tx;    // quad column 0..127
    const int ibase = blockIdx.y * 8;
    const int i0 = ibase + ty;              // this warp's row
    const int t0 = blockIdx.z * TPC;

    const ulonglong2* __restrict__ base = (const ulonglong2*)inF;
    const int FR = HH * W4;                 // quads per channel-frame
    const size_t FS = (size_t)2 * FR;       // quads per timestep

    const int cl = (jb - 1) & 127, cr = (jb + 1) & 127;
    const int o_c = i0 * W4 + jb;
    const int o_l = i0 * W4 + cl;
    const int o_r = i0 * W4 + cr;

    // edge warps fetch the block-外 halo rows
    const bool edge0 = (ty == 0);
    const bool edge7 = (ty == 7);
    int o_h0 = 0, o_h1 = 0, smh = 0;
    if (edge0) { o_h0 = ((ibase -  2) & 511) * W4 + jb; o_h1 = ((ibase - 1) & 511) * W4 + jb; smh = 0;  }
    if (edge7) { o_h0 = ((ibase +  8) & 511) * W4 + jb; o_h1 = ((ibase + 9) & 511) * W4 + jb; smh = 10; }

    const ulonglong2* pu = base + (size_t)(t0 * 2) * FR;   // u at t; v at +FR

    const float ccf = 0.1f * (-5.0f) * 25.0f;
    const float cnf = 0.1f * (4.0f / 3.0f) * 25.0f;
    const float cff = 0.1f * (-1.0f / 12.0f) * 25.0f;
    const u64 CC   = pk(ccf, ccf);
    const u64 CN   = pk(cnf, cnf);
    const u64 CF   = pk(cff, cff);
    const u64 ONE  = pk(1.0f, 1.0f);
    const u64 NIDT = pk(-80.0f, -80.0f);

    const bool rowdup = (i0 == 0);
    const bool coldup = (jb == 0);

    // carried centers at time t
    ulonglong2 u = pu[o_c];
    ulonglong2 v = pu[FR + o_c];

    u64 aUl = 0, aUh = 0, aVl = 0, aVh = 0;

    #pragma unroll 1
    for (int it = 0; it < TPC; ++it) {
        // early global loads: next-t centers (the DRAM stream)
        const ulonglong2 nu = pu[FS + o_c];
        const ulonglong2 nv = pu[FS + FR + o_c];
        // lane-edge horizontal halves (8B each), L2-hot
        u64 ule = 0, vle = 0, ure = 0, vre = 0;
        if (tx == 0) {
            ule = ((const u64*)(pu + o_l))[1];
            vle = ((const u64*)(pu + FR + o_l))[1];
        }
        if (tx == 31) {
            ure = ((const u64*)(pu + o_r))[0];
            vre = ((const u64*)(pu + FR + o_r))[0];
        }
        // block-edge vertical halo rows, L2-hot
        ulonglong2 hu0, hu1, hv0, hv1;
        if (edge0 || edge7) {
            hu0 = pu[o_h0]; hu1 = pu[o_h1];
            hv0 = pu[FR + o_h0]; hv1 = pu[FR + o_h1];
        }

        __syncthreads();                     // prior LDS complete before overwrite
        smu[(ty + 2) * 32 + tx] = u;
        smv[(ty + 2) * 32 + tx] = v;
        if (edge0 || edge7) {
            smu[smh * 32 + tx] = hu0;  smu[(smh + 1) * 32 + tx] = hu1;
            smv[smh * 32 + tx] = hv0;  smv[(smh + 1) * 32 + tx] = hv1;
        }
        __syncthreads();                     // stores visible

        // vertical halos from smem
        const ulonglong2 um2 = smu[ ty      * 32 + tx];
        const ulonglong2 um1 = smu[(ty + 1) * 32 + tx];
        const ulonglong2 up1 = smu[(ty + 3) * 32 + tx];
        const ulonglong2 up2 = smu[(ty + 4) * 32 + tx];
        const ulonglong2 vm2 = smv[ ty      * 32 + tx];
        const ulonglong2 vm1 = smv[(ty + 1) * 32 + tx];
        const ulonglong2 vp1 = smv[(ty + 3) * 32 + tx];
        const ulonglong2 vp2 = smv[(ty + 4) * 32 + tx];

        // horizontal neighbors via shuffles of carried centers
        u64 ul = __shfl_up_sync(0xffffffffu, u.y, 1);
        u64 vl = __shfl_up_sync(0xffffffffu, v.y, 1);
        u64 ur = __shfl_down_sync(0xffffffffu, u.x, 1);
        u64 vr = __shfl_down_sync(0xffffffffu, v.x, 1);
        if (tx == 0)  { ul = ule; vl = vle; }
        if (tx == 31) { ur = ure; vr = vre; }

        u64 LUl, LUh, DUl, DUh, LVl, LVh, DVl, DVh;
        lap_d(u.x, u.y, ul, ur, um1.x, um1.y, up1.x, up1.y,
              um2.x, um2.y, up2.x, up2.y, nu.x, nu.y, CC, CN, CF,
              LUl, LUh, DUl, DUh);
        lap_d(v.x, v.y, vl, vr, vm1.x, vm1.y, vp1.x, vp1.y,
              vm2.x, vm2.y, vp2.x, vp2.y, nv.x, nv.y, CC, CN, CF,
              LVl, LVh, DVl, DVh);

        const u64 sl = ffma2(u.x, u.x, fmul2(v.x, v.x));
        const u64 sh = ffma2(u.y, u.y, fmul2(v.y, v.y));
        const u64 pl = fsub2(ONE, sl);
        const u64 ph = fsub2(ONE, sh);

        const u64 rul = ffma2(DUl, NIDT, ffma2(pl, u.x, ffma2(sl, v.x, LUl)));
        const u64 ruh = ffma2(DUh, NIDT, ffma2(ph, u.y, ffma2(sh, v.y, LUh)));
        const u64 rvl = ffma2(DVl, NIDT, ffma2(pl, v.x, fsub2(LVl, fmul2(sl, u.x))));
        const u64 rvh = ffma2(DVh, NIDT, ffma2(ph, v.y, fsub2(LVh, fmul2(sh, u.y))));

        aUl = ffma2(rul, rul, aUl);
        aUh = ffma2(ruh, ruh, aUh);
        aVl = ffma2(rvl, rvl, aVl);
        aVh = ffma2(rvh, rvh, aVh);

        if (rowdup) {   // duplicated row 0 (warp-uniform)
            aUl = ffma2(rul, rul, aUl);
            aUh = ffma2(ruh, ruh, aUh);
            aVl = ffma2(rvl, rvl, aVl);
            aVh = ffma2(rvh, rvh, aVh);
        }
        if (coldup) {   // duplicated col 0 (lane 0 of blockIdx.x==0)
            float a, b;
            upk(rul, a, b); const u64 eu = pk(a, 0.0f);
            upk(rvl, a, b); const u64 ev = pk(a, 0.0f);
            aUl = ffma2(eu, eu, aUl);
            aVl = ffma2(ev, ev, aVl);
            if (rowdup) {   // corner (0,0): total weight 4
                aUl = ffma2(eu, eu, aUl);
                aVl = ffma2(ev, ev, aVl);
            }
        }

        u = nu; v = nv;
        pu += FS;
    }

    // fold packed accumulators
    float a, b, c, d;
    upk(aUl, a, b); upk(aUh, c, d);
    float sum_u = (a + b) + (c + d);
    upk(aVl, a, b); upk(aVh, c, d);
    float sum_v = (a + b) + (c + d);

    #pragma unroll
    for (int off = 16; off > 0; off >>= 1) {
        sum_u += __shfl_down_sync(0xffffffffu, sum_u, off);
        sum_v += __shfl_down_sync(0xffffffffu, sum_v, off);
    }

    __shared__ float su[8], sv[8];
    __shared__ bool isLast;
    if (tx == 0) { su[ty] = sum_u; sv[ty] = sum_v; }
    __syncthreads();

    const int tid = ty * 32 + tx;
    if (tid == 0) {
        float pa = 0.0f, pb = 0.0f;
        #pragma unroll
        for (int k = 0; k < 8; ++k) { pa += su[k]; pb += sv[k]; }
        const int blk = (blockIdx.z * GY + blockIdx.y) * GX + blockIdx.x;
        g_part[blk * 2 + 0] = pa;
        g_part[blk * 2 + 1] = pb;
        __threadfence();
        const unsigned int old = atomicAdd(&g_count, 1);
        isLast = (old == (unsigned int)(NBLK - 1));
    }
    __syncthreads();

    if (isLast) {
        __threadfence();
        double da = 0.0, db = 0.0;
        for (int k = tid; k < NBLK; k += 256) {
            da += (double)g_part[2 * k + 0];
            db += (double)g_part[2 * k + 1];
        }
        __shared__ double sa[256], sb[256];
        sa[tid] = da; sb[tid] = db;
        __syncthreads();
        #pragma unroll
        for (int s = 128; s > 0; s >>= 1) {
            if (tid < s) { sa[tid] += sa[tid + s]; sb[tid] += sb[tid + s]; }
            __syncthreads();
        }
        if (tid == 0) {
            out[0] = (float)(sa[0] / DENOM);
            out[1] = (float)(sb[0] / DENOM);
            g_count = 0;
        }
    }
}

extern "C" void kernel_launch(void* const* d_in, const int* in_sizes, int n_in,
                              void* d_out, int out_size) {
    (void)in_sizes; (void)n_in; (void)out_size;
    const float* in = (const float*)d_in[0];
    float* out = (float*)d_out;

    dim3 grid(GX, GY, TC);
    dim3 block(32, 8);
    pde_kernel<<<grid, block>>>(in, out);
}

// round 5
// speedup vs baseline: 1.6245x; 1.6245x over previous
#include <cuda_runtime.h>

// Geometry: thread owns 4 rows x 2 cols (one u64). Warp = 32 u64 = 64 cols.
#define HH    512
#define W2    256            // u64 per row
#define FR2   (HH * W2)      // u64 per channel-frame
#define FS2   (2 * FR2)      // u64 per timestep
#define TC    9              // t-chunks
#define TPC   22             // 198 / 9
#define GX    8              // 256 u64-cols / 32 lanes
#define GY    16             // 512 rows / (8 warps * 4 rows)
#define NBLK  (GX * GY * TC) // 1152

#define DENOM 52107462.0     // 198 * 513 * 513
#define SCALE 6400.0         // (1/DT)^2 deferred from the residual

typedef unsigned long long u64;

__device__ float g_part[NBLK * 2];
__device__ unsigned int g_count = 0;

// ---------- packed f32x2 helpers ----------
__device__ __forceinline__ u64 pk(float a, float b) {
    u64 r; asm("mov.b64 %0, {%1, %2};" : "=l"(r) : "f"(a), "f"(b)); return r;
}
__device__ __forceinline__ void upk(u64 v, float& a, float& b) {
    asm("mov.b64 {%0, %1}, %2;" : "=f"(a), "=f"(b) : "l"(v));
}
__device__ __forceinline__ u64 fadd2(u64 a, u64 b) {
    u64 d; asm("add.rn.f32x2 %0, %1, %2;" : "=l"(d) : "l"(a), "l"(b)); return d;
}
__device__ __forceinline__ u64 fsub2(u64 a, u64 b) {
    u64 d; asm("sub.rn.f32x2 %0, %1, %2;" : "=l"(d) : "l"(a), "l"(b)); return d;
}
__device__ __forceinline__ u64 fmul2(u64 a, u64 b) {
    u64 d; asm("mul.rn.f32x2 %0, %1, %2;" : "=l"(d) : "l"(a), "l"(b)); return d;
}
__device__ __forceinline__ u64 ffma2(u64 a, u64 b, u64 c) {
    u64 d; asm("fma.rn.f32x2 %0, %1, %2, %3;" : "=l"(d) : "l"(a), "l"(b), "l"(c)); return d;
}

__global__ __launch_bounds__(256, 3)
void pde_kernel(const float* __restrict__ inF, float* __restrict__ out)
{
    const int tx = threadIdx.x;               // lane
    const int ty = threadIdx.y;               // warp
    const int cp = blockIdx.x * 32 + tx;      // u64 column 0..255
    const int i0 = blockIdx.y * 32 + ty * 4;  // first of 4 rows
    const int t0 = blockIdx.z * TPC;

    const u64* __restrict__ base = (const u64*)inF;

    // center base: (t0, ch0, i0, cp)
    const u64* pC  = base + (size_t)t0 * FS2 + i0 * W2 + cp;
    // wrapped halo-row bases
    const u64* pm2 = base + (size_t)t0 * FS2 + ((i0 - 2) & 511) * W2 + cp;
    const u64* pm1 = base + (size_t)t0 * FS2 + ((i0 - 1) & 511) * W2 + cp;
    const u64* pp4 = base + (size_t)t0 * FS2 + ((i0 + 4) & 511) * W2 + cp;
    const u64* pp5 = base + (size_t)t0 * FS2 + ((i0 + 5) & 511) * W2 + cp;
    // edge-lane horizontal neighbor base (lane0: left u64; lane31: right u64)
    const int ecp = ((tx == 31) ? (cp + 1) : (cp - 1)) & 255;
    const u64* pE  = base + (size_t)t0 * FS2 + i0 * W2 + ecp;
    const bool isedge = (tx == 0) | (tx == 31);

    // constants (MU and DX^2 folded into stencil; 1/DT deferred)
    const float ccf = 0.1f * (-5.0f) * 25.0f;
    const float cnf = 0.1f * (4.0f / 3.0f) * 25.0f;
    const float cff = 0.1f * (-1.0f / 12.0f) * 25.0f;
    const u64 CC  = pk(ccf, ccf);
    const u64 CN  = pk(cnf, cnf);
    const u64 CF  = pk(cff, cff);
    const u64 MDT = pk(-0.0125f, -0.0125f);

    const bool rowdup = (i0 == 0);                    // thread's row 0 is grid row 0
    const bool coldup = (cp == 0);                    // px0 of lane 0 of bx==0 is col 0

    // carried centers at time t: 4 rows x 2 channels
    u64 cu0 = pC[0 * W2],        cu1 = pC[1 * W2];
    u64 cu2 = pC[2 * W2],        cu3 = pC[3 * W2];
    u64 cv0 = pC[FR2 + 0 * W2],  cv1 = pC[FR2 + 1 * W2];
    u64 cv2 = pC[FR2 + 2 * W2],  cv3 = pC[FR2 + 3 * W2];

    u64 aU = 0, aV = 0;

    #pragma unroll 1
    for (int it = 0; it < TPC; ++it) {
        // ---- loads (all independent; the only DRAM stream is next-t centers)
        const u64 hm2u = pm2[0],   hm2v = pm2[FR2];
        const u64 hm1u = pm1[0],   hm1v = pm1[FR2];
        const u64 hp4u = pp4[0],   hp4v = pp4[FR2];
        const u64 hp5u = pp5[0],   hp5v = pp5[FR2];

        const u64 nu0 = pC[FS2 + 0 * W2],       nu1 = pC[FS2 + 1 * W2];
        const u64 nu2 = pC[FS2 + 2 * W2],       nu3 = pC[FS2 + 3 * W2];
        const u64 nv0 = pC[FS2 + FR2 + 0 * W2], nv1 = pC[FS2 + FR2 + 1 * W2];
        const u64 nv2 = pC[FS2 + FR2 + 2 * W2], nv3 = pC[FS2 + FR2 + 3 * W2];

        u64 eu0 = 0, eu1 = 0, eu2 = 0, eu3 = 0;
        u64 ev0 = 0, ev1 = 0, ev2 = 0, ev3 = 0;
        if (isedge) {
            eu0 = pE[0 * W2];       eu1 = pE[1 * W2];
            eu2 = pE[2 * W2];       eu3 = pE[3 * W2];
            ev0 = pE[FR2 + 0 * W2]; ev1 = pE[FR2 + 1 * W2];
            ev2 = pE[FR2 + 2 * W2]; ev3 = pE[FR2 + 3 * W2];
        }

        // row stacks (index r: rows i0-2 .. i0+5)
        const u64 RU[8] = {hm2u, hm1u, cu0, cu1, cu2, cu3, hp4u, hp5u};
        const u64 RV[8] = {hm2v, hm1v, cv0, cv1, cv2, cv3, hp4v, hp5v};
        const u64 NU[4] = {nu0, nu1, nu2, nu3};
        const u64 NV[4] = {nv0, nv1, nv2, nv3};
        const u64 EU[4] = {eu0, eu1, eu2, eu3};
        const u64 EV[4] = {ev0, ev1, ev2, ev3};

        #pragma unroll
        for (int r = 0; r < 4; ++r) {
            const u64 cu = RU[r + 2];
            const u64 cv = RV[r + 2];

            // horizontal neighbor u64s via warp shuffle (edge lanes from gmem)
            u64 Lu = __shfl_up_sync(0xffffffffu, cu, 1);
            u64 Lv = __shfl_up_sync(0xffffffffu, cv, 1);
            u64 Ru = __shfl_down_sync(0xffffffffu, cu, 1);
            u64 Rv = __shfl_down_sync(0xffffffffu, cv, 1);
            if (tx == 0)  { Lu = EU[r]; Lv = EV[r]; }
            if (tx == 31) { Ru = EU[r]; Rv = EV[r]; }

            float l0, l1, c0, c1, q0, q1;

            // ---- u laplacian
            upk(Lu, l0, l1); upk(cu, c0, c1); upk(Ru, q0, q1);
            const u64 nearU = fadd2(fadd2(pk(l1, c0), pk(c1, q0)),
                                    fadd2(RU[r + 1], RU[r + 3]));
            const u64 farU  = fadd2(fadd2(Lu, Ru),
                                    fadd2(RU[r], RU[r + 4]));
            const u64 lapU  = ffma2(CN, nearU, ffma2(CF, farU, fmul2(CC, cu)));

            // ---- v laplacian
            upk(Lv, l0, l1); upk(cv, c0, c1); upk(Rv, q0, q1);
            const u64 nearV = fadd2(fadd2(pk(l1, c0), pk(c1, q0)),
                                    fadd2(RV[r + 1], RV[r + 3]));
            const u64 farV  = fadd2(fadd2(Lv, Rv),
                                    fadd2(RV[r], RV[r + 4]));
            const u64 lapV  = ffma2(CN, nearV, ffma2(CF, farV, fmul2(CC, cv)));

            // ---- residuals (scaled by DT; squared scale applied at the end)
            const u64 s  = ffma2(cu, cu, fmul2(cv, cv));
            const u64 du = fsub2(NU[r], cu);
            const u64 dv = fsub2(NV[r], cv);
            const u64 t1 = fsub2(cv, cu);
            const u64 t2 = fadd2(cv, cu);
            // X_u = u + lap_u + s*(v-u);  X_v = v + lap_v - s*(v+u)
            const u64 Xu = fadd2(cu, ffma2(s, t1, lapU));
            const u64 Xv = fadd2(cv, fsub2(lapV, fmul2(s, t2)));
            const u64 ru = ffma2(Xu, MDT, du);   // du - DT*Xu
            const u64 rv = ffma2(Xv, MDT, dv);

            aU = ffma2(ru, ru, aU);
            aV = ffma2(rv, rv, aV);

            if (r == 0 && rowdup) {              // duplicated grid row 0
                aU = ffma2(ru, ru, aU);
                aV = ffma2(rv, rv, aV);
            }
            if (coldup) {                         // duplicated grid col 0 (px0)
                float a, b;
                upk(ru, a, b); const u64 e1 = pk(a, 0.0f);
                upk(rv, a, b); const u64 e2 = pk(a, 0.0f);
                aU = ffma2(e1, e1, aU);
                aV = ffma2(e2, e2, aV);
                if (r == 0 && rowdup) {          // corner (0,0): weight 4
                    aU = ffma2(e1, e1, aU);
                    aV = ffma2(e2, e2, aV);
                }
            }
        }

        // slide in time
        cu0 = nu0; cu1 = nu1; cu2 = nu2; cu3 = nu3;
        cv0 = nv0; cv1 = nv1; cv2 = nv2; cv3 = nv3;
        pC += FS2; pm2 += FS2; pm1 += FS2; pp4 += FS2; pp5 += FS2; pE += FS2;
    }

    // fold packed accumulators
    float a, b;
    upk(aU, a, b); float sum_u = a + b;
    upk(aV, a, b); float sum_v = a + b;

    #pragma unroll
    for (int off = 16; off > 0; off >>= 1) {
        sum_u += __shfl_down_sync(0xffffffffu, sum_u, off);
        sum_v += __shfl_down_sync(0xffffffffu, sum_v, off);
    }

    __shared__ float su[8], sv[8];
    __shared__ bool isLast;
    if (tx == 0) { su[ty] = sum_u; sv[ty] = sum_v; }
    __syncthreads();

    const int tid = ty * 32 + tx;
    if (tid == 0) {
        float pa = 0.0f, pb = 0.0f;
        #pragma unroll
        for (int k = 0; k < 8; ++k) { pa += su[k]; pb += sv[k]; }
        const int blk = (blockIdx.z * GY + blockIdx.y) * GX + blockIdx.x;
        g_part[blk * 2 + 0] = pa;
        g_part[blk * 2 + 1] = pb;
        __threadfence();
        const unsigned int old = atomicAdd(&g_count, 1);
        isLast = (old == (unsigned int)(NBLK - 1));
    }
    __syncthreads();

    if (isLast) {
        __threadfence();
        double da = 0.0, db = 0.0;
        for (int k = tid; k < NBLK; k += 256) {
            da += (double)g_part[2 * k + 0];
            db += (double)g_part[2 * k + 1];
        }
        __shared__ double sa[256], sb[256];
        sa[tid] = da; sb[tid] = db;
        __syncthreads();
        #pragma unroll
        for (int s = 128; s > 0; s >>= 1) {
            if (tid < s) { sa[tid] += sa[tid + s]; sb[tid] += sb[tid + s]; }
            __syncthreads();
        }
        if (tid == 0) {
            out[0] = (float)(sa[0] * SCALE / DENOM);
            out[1] = (float)(sb[0] * SCALE / DENOM);
            g_count = 0;
        }
    }
}

extern "C" void kernel_launch(void* const* d_in, const int* in_sizes, int n_in,
                              void* d_out, int out_size) {
    (void)in_sizes; (void)n_in; (void)out_size;
    const float* in = (const float*)d_in[0];
    float* out = (float*)d_out;

    dim3 grid(GX, GY, TC);
    dim3 block(32, 8);
    pde_kernel<<<grid, block>>>(in, out);
}